// round 7
// baseline (speedup 1.0000x reference)
#include <cuda_runtime.h>
#include <math.h>

// Problem constants (fixed by reference: H = W = 2048)
#define H_ 2048
#define W_ 2048
#define HW_ (H_ * W_)
#define LOG2W 11

// ---------------------------------------------------------------------------
// Kernel 1: fused separable gaussian (1x5 then 5x1, zero pad 2).
// Tile 128x32 per block/channel. Identical to R6 (bit-exact, near traffic floor).
// ---------------------------------------------------------------------------
#define TILE_X 128
#define TILE_Y 32
#define SROWS (TILE_Y + 4)
#define TX4 (TILE_X / 4)

__global__ void blur_f_k(const float* __restrict__ img, const float* __restrict__ g,
                         float* __restrict__ blurred) {
    __shared__ float4 sh4[SROWS][TX4];
    const int c = blockIdx.z;
    const int tileX0 = blockIdx.x * TILE_X;
    const int tileY0 = blockIdx.y * TILE_Y;
    const int t = threadIdx.x;          // 0..255
    const float* im = img + c * HW_;
    const float g0 = g[0], g1 = g[1], g2 = g[2], g3 = g[3], g4 = g[4];
    const float4 z4 = make_float4(0.f, 0.f, 0.f, 0.f);

    for (int u = t; u < SROWS * TX4; u += 256) {
        int r   = u >> 5;
        int cx4 = u & 31;
        int gy  = tileY0 - 2 + r;
        float4 o = z4;
        if (gy >= 0 && gy < H_) {
            const float4* row4 = (const float4*)(im + gy * W_);
            int gx = tileX0 + cx4 * 4;
            float4 L = (gx >= 4)     ? __ldg(row4 + (gx >> 2) - 1) : z4;
            float4 M =                 __ldg(row4 + (gx >> 2));
            float4 R = (gx + 4 < W_) ? __ldg(row4 + (gx >> 2) + 1) : z4;
            float v0 = L.z, v1 = L.w;
            float v2 = M.x, v3 = M.y, v4 = M.z, v5 = M.w;
            float v6 = R.x, v7 = R.y;
            o.x = fmaf(g4, v4, fmaf(g3, v3, fmaf(g2, v2, fmaf(g1, v1, __fmul_rn(g0, v0)))));
            o.y = fmaf(g4, v5, fmaf(g3, v4, fmaf(g2, v3, fmaf(g1, v2, __fmul_rn(g0, v1)))));
            o.z = fmaf(g4, v6, fmaf(g3, v5, fmaf(g2, v4, fmaf(g1, v3, __fmul_rn(g0, v2)))));
            o.w = fmaf(g4, v7, fmaf(g3, v6, fmaf(g2, v5, fmaf(g1, v4, __fmul_rn(g0, v3)))));
        }
        sh4[r][cx4] = o;
    }
    __syncthreads();

    {
        int ty0 = (t >> 5) * 4;
        int tx4 = t & 31;
        float4 r0 = sh4[ty0    ][tx4];
        float4 r1 = sh4[ty0 + 1][tx4];
        float4 r2 = sh4[ty0 + 2][tx4];
        float4 r3 = sh4[ty0 + 3][tx4];
        float4 r4 = sh4[ty0 + 4][tx4];
        float4 r5 = sh4[ty0 + 5][tx4];
        float4 r6 = sh4[ty0 + 6][tx4];
        float4 r7 = sh4[ty0 + 7][tx4];
        float* base = blurred + c * HW_ + (tileY0 + ty0) * W_ + tileX0 + tx4 * 4;

#define VBLUR(d, a0, a1, a2, a3, a4)                                                               \
        {                                                                                           \
            float4 o;                                                                               \
            o.x = fmaf(g4, a4.x, fmaf(g3, a3.x, fmaf(g2, a2.x, fmaf(g1, a1.x, __fmul_rn(g0, a0.x))))); \
            o.y = fmaf(g4, a4.y, fmaf(g3, a3.y, fmaf(g2, a2.y, fmaf(g1, a1.y, __fmul_rn(g0, a0.y))))); \
            o.z = fmaf(g4, a4.z, fmaf(g3, a3.z, fmaf(g2, a2.z, fmaf(g1, a1.z, __fmul_rn(g0, a0.z))))); \
            o.w = fmaf(g4, a4.w, fmaf(g3, a3.w, fmaf(g2, a2.w, fmaf(g1, a1.w, __fmul_rn(g0, a0.w))))); \
            *(float4*)(base + (d) * W_) = o;                                                        \
        }
        VBLUR(0, r0, r1, r2, r3, r4)
        VBLUR(1, r1, r2, r3, r4, r5)
        VBLUR(2, r2, r3, r4, r5, r6)
        VBLUR(3, r3, r4, r5, r6, r7)
#undef VBLUR
    }
}

// ---------------------------------------------------------------------------
// Kernel 2: FUSED sobel + NMS per 64x16 tile.
// Stage A: grad on 18x72 halo region (halo=1) into smem; central region also
//          gets orient (atan2 pipeline, bit-exact) + early, written to gmem;
//          q index stored as bytes in smem.
// Stage B: NMS entirely from smem (stored grad values -> bit-identical to
//          reading grad back from gmem). Out-of-image smem = 0 == zero pad.
// ---------------------------------------------------------------------------
#define STX 64
#define STY 16
#define GROWS (STY + 2)       // 18
#define GCOLS_U ((STX + 8) / 4) // 18 float4 units, cols x0-4 .. x0+67

__global__ void sobel_nms_k(const float* __restrict__ blurred,
                            const float* __restrict__ thr_p,
                            float* __restrict__ grad,
                            float* __restrict__ orient,
                            float* __restrict__ early,
                            float* __restrict__ thin,
                            float* __restrict__ thresh) {
    __shared__ float grad_s[GROWS][GCOLS_U * 4];   // 18 x 72 floats
    __shared__ unsigned char qs[STY][STX];
    const int x0 = blockIdx.x * STX;
    const int y0 = blockIdx.y * STY;
    const int t = threadIdx.x;          // 0..255
    const float thr = __ldg(thr_p);
    const float C = (float)(180.0 / 3.14159);   // NOTE: 3.14159, not pi

    // ---- Stage A: grad (+orient/early for central) ----
    for (int u = t; u < GROWS * GCOLS_U; u += 256) {
        int r  = u / GCOLS_U;            // 0..17, grad_s row; image y = y0-1+r
        int cu = u - r * GCOLS_U;        // 0..17, unit;    image x = x0-4+cu*4
        int gy = y0 - 1 + r;
        int gx = x0 - 4 + cu * 4;
        float4 gm4 = make_float4(0.f, 0.f, 0.f, 0.f);
        float* gmA = (float*)&gm4;

        if (gy >= 0 && gy < H_ && gx >= 0 && gx < W_) {
            bool ym = (gy > 0), yp = (gy < H_ - 1);
            bool xl = (gx > 0), xr = (gx + 4 < W_);
            bool central = (r >= 1 && r <= STY) && (cu >= 1 && cu <= STX / 4);

            float mag[4] = {0.f, 0.f, 0.f, 0.f};
            float sx[4]  = {0.f, 0.f, 0.f, 0.f};
            float sy[4]  = {0.f, 0.f, 0.f, 0.f};
#pragma unroll
            for (int c = 0; c < 3; ++c) {
                const float* b = blurred + c * HW_ + gy * W_ + gx;
                float tp[6], md[6], bt[6];
                if (ym) {
                    float4 v = __ldg((const float4*)(b - W_));
                    tp[1] = v.x; tp[2] = v.y; tp[3] = v.z; tp[4] = v.w;
                    tp[0] = xl ? __ldg(b - W_ - 1) : 0.f;
                    tp[5] = xr ? __ldg(b - W_ + 4) : 0.f;
                } else {
                    tp[0] = tp[1] = tp[2] = tp[3] = tp[4] = tp[5] = 0.f;
                }
                {
                    float4 v = __ldg((const float4*)b);
                    md[1] = v.x; md[2] = v.y; md[3] = v.z; md[4] = v.w;
                    md[0] = xl ? __ldg(b - 1) : 0.f;
                    md[5] = xr ? __ldg(b + 4) : 0.f;
                }
                if (yp) {
                    float4 v = __ldg((const float4*)(b + W_));
                    bt[1] = v.x; bt[2] = v.y; bt[3] = v.z; bt[4] = v.w;
                    bt[0] = xl ? __ldg(b + W_ - 1) : 0.f;
                    bt[5] = xr ? __ldg(b + W_ + 4) : 0.f;
                } else {
                    bt[0] = bt[1] = bt[2] = bt[3] = bt[4] = bt[5] = 0.f;
                }
#pragma unroll
                for (int i = 0; i < 4; ++i) {
                    float a00 = tp[i], a01 = tp[i + 1], a02 = tp[i + 2];
                    float a10 = md[i],                  a12 = md[i + 2];
                    float a20 = bt[i], a21 = bt[i + 1], a22 = bt[i + 2];
                    float gxx = a00;
                    gxx = fmaf(-1.f, a02, gxx);
                    gxx = fmaf( 2.f, a10, gxx);
                    gxx = fmaf(-2.f, a12, gxx);
                    gxx = fmaf( 1.f, a20, gxx);
                    gxx = fmaf(-1.f, a22, gxx);
                    float gyy = a00;
                    gyy = fmaf( 2.f, a01, gyy);
                    gyy = fmaf( 1.f, a02, gyy);
                    gyy = fmaf(-1.f, a20, gyy);
                    gyy = fmaf(-2.f, a21, gyy);
                    gyy = fmaf(-1.f, a22, gyy);

                    mag[i] = __fadd_rn(mag[i], sqrtf(fmaf(gxx, gxx, __fmul_rn(gyy, gyy))));
                    sx[i]  = __fadd_rn(sx[i], gxx);
                    sy[i]  = __fadd_rn(sy[i], gyy);
                }
            }
            gmA[0] = mag[0]; gmA[1] = mag[1]; gmA[2] = mag[2]; gmA[3] = mag[3];

            if (central) {
                int ry = r - 1;                  // 0..15
                int cxl = (cu - 1) * 4;          // 0..60, local col of pixel 0
                float4 or4, ea4;
                float* orA = (float*)&or4;
                float* eaA = (float*)&ea4;
#pragma unroll
                for (int i = 0; i < 4; ++i) {
                    float o  = atan2f(sy[i], sx[i]);   // libdevice __nv_atan2f
                    float ov = __fmul_rn(o, C);
                    float tt = __fdiv_rn(__fadd_rn(ov, 180.0f), 45.0f);
                    float q  = rintf(tt);              // half-even (jnp.round)
                    orA[i] = __fmul_rn(q, 45.0f);
                    eaA[i] = (mag[i] < thr) ? 0.f : mag[i];
                    qs[ry][cxl + i] = (unsigned char)(int)q;
                }
                int idx = gy * W_ + gx;
                *(float4*)(grad + idx)   = gm4;
                *(float4*)(orient + idx) = or4;
                *(float4*)(early + idx)  = ea4;
            }
        }
        *(float4*)&grad_s[r][cu * 4] = gm4;
    }
    __syncthreads();

    // ---- Stage B: NMS from smem ----
    // dir k offsets (dy,dx): 0:(0,1) 1:(1,1) 2:(1,0) 3:(1,-1) 4:(0,-1)
    //                        5:(-1,-1) 6:(-1,0) 7:(-1,1)
    const unsigned DYP = 0x00012221u;   // nibble k = dy[k]+1
    const unsigned DXP = 0x21000122u;   // nibble k = dx[k]+1

    int rr = t >> 4;            // 0..15, local row
    int uu = t & 15;            // 0..15, local float4 unit
    int cb = 3 + uu * 4;        // smem col of (pixel x - 1)

    float tp[6], md[6], bt[6];
#pragma unroll
    for (int j = 0; j < 6; ++j) {
        tp[j] = grad_s[rr][cb + j];
        md[j] = grad_s[rr + 1][cb + j];
        bt[j] = grad_s[rr + 2][cb + j];
    }

    float4 th4, ts4;
    float* thA = (float*)&th4;
    float* tsA = (float*)&ts4;
#pragma unroll
    for (int i = 0; i < 4; ++i) {
        float gm = md[i + 1];
        int q  = qs[rr][uu * 4 + i];
        int kp = q & 7;
        int kn = (q + 4) & 7;

        int dyp = (int)((DYP >> (kp * 4)) & 3u) - 1;
        int dxp = (int)((DXP >> (kp * 4)) & 3u) - 1;
        int dyn = (int)((DYP >> (kn * 4)) & 3u) - 1;
        int dxn = (int)((DXP >> (kn * 4)) & 3u) - 1;

        float tT = (dxp < 0) ? tp[i] : ((dxp > 0) ? tp[i + 2] : tp[i + 1]);
        float tM = (dxp < 0) ? md[i] : ((dxp > 0) ? md[i + 2] : md[i + 1]);
        float tB = (dxp < 0) ? bt[i] : ((dxp > 0) ? bt[i + 2] : bt[i + 1]);
        float np = (dyp < 0) ? tT : ((dyp > 0) ? tB : tM);

        float uT = (dxn < 0) ? tp[i] : ((dxn > 0) ? tp[i + 2] : tp[i + 1]);
        float uM = (dxn < 0) ? md[i] : ((dxn > 0) ? md[i + 2] : md[i + 1]);
        float uB = (dxn < 0) ? bt[i] : ((dxn > 0) ? bt[i + 2] : bt[i + 1]);
        float nn = (dyn < 0) ? uT : ((dyn > 0) ? uB : uM);

        float pos = __fadd_rn(gm, -np);
        float neg = __fadd_rn(gm, -nn);
        float tv = (fminf(pos, neg) > 0.f) ? gm : 0.f;
        thA[i] = tv;
        tsA[i] = (tv < thr) ? 0.f : tv;
    }
    int oidx = (y0 + rr) * W_ + x0 + uu * 4;
    *(float4*)(thin + oidx)   = th4;
    *(float4*)(thresh + oidx) = ts4;
}

// ---------------------------------------------------------------------------
// Launch
// Inputs: img[3HW], threshold[1], gauss_h[5], gauss_v[5], sobel_h[9],
//         sobel_v[9], dir_w[72]
// Output: [0,3HW) blurred | [3HW,4HW) grad | [4HW,5HW) orient |
//         [5HW,6HW) thin | [6HW,7HW) thresholded | [7HW,8HW) early
// ---------------------------------------------------------------------------
extern "C" void kernel_launch(void* const* d_in, const int* in_sizes, int n_in,
                              void* d_out, int out_size) {
    const float* img   = (const float*)d_in[0];
    const float* thr   = (const float*)d_in[1];
    const float* gauss = (const float*)d_in[2];

    float* out      = (float*)d_out;
    float* blurred  = out;
    float* grad     = out + 3 * HW_;
    float* orient   = out + 4 * HW_;
    float* thin     = out + 5 * HW_;
    float* thresh   = out + 6 * HW_;
    float* early    = out + 7 * HW_;

    dim3 bgrid(W_ / TILE_X, H_ / TILE_Y, 3);   // 16 x 64 x 3
    blur_f_k<<<bgrid, 256>>>(img, gauss, blurred);

    dim3 sgrid(W_ / STX, H_ / STY);            // 32 x 128
    sobel_nms_k<<<sgrid, 256>>>(blurred, thr, grad, orient, early, thin, thresh);
}

// round 8
// speedup vs baseline: 1.2247x; 1.2247x over previous
#include <cuda_runtime.h>
#include <math.h>

// Problem constants (fixed by reference: H = W = 2048)
#define H_ 2048
#define W_ 2048
#define HW_ (H_ * W_)
#define LOG2W 11

// ---------------------------------------------------------------------------
// Kernel 1: fused separable gaussian (1x5 then 5x1, zero pad 2).
// Tile 128x32 per block/channel. Identical to R6 (bit-exact).
// ---------------------------------------------------------------------------
#define TILE_X 128
#define TILE_Y 32
#define SROWS (TILE_Y + 4)
#define TX4 (TILE_X / 4)

__global__ void blur_f_k(const float* __restrict__ img, const float* __restrict__ g,
                         float* __restrict__ blurred) {
    __shared__ float4 sh4[SROWS][TX4];
    const int c = blockIdx.z;
    const int tileX0 = blockIdx.x * TILE_X;
    const int tileY0 = blockIdx.y * TILE_Y;
    const int t = threadIdx.x;          // 0..255
    const float* im = img + c * HW_;
    const float g0 = g[0], g1 = g[1], g2 = g[2], g3 = g[3], g4 = g[4];
    const float4 z4 = make_float4(0.f, 0.f, 0.f, 0.f);

    for (int u = t; u < SROWS * TX4; u += 256) {
        int r   = u >> 5;
        int cx4 = u & 31;
        int gy  = tileY0 - 2 + r;
        float4 o = z4;
        if (gy >= 0 && gy < H_) {
            const float4* row4 = (const float4*)(im + gy * W_);
            int gx = tileX0 + cx4 * 4;
            float4 L = (gx >= 4)     ? __ldg(row4 + (gx >> 2) - 1) : z4;
            float4 M =                 __ldg(row4 + (gx >> 2));
            float4 R = (gx + 4 < W_) ? __ldg(row4 + (gx >> 2) + 1) : z4;
            float v0 = L.z, v1 = L.w;
            float v2 = M.x, v3 = M.y, v4 = M.z, v5 = M.w;
            float v6 = R.x, v7 = R.y;
            o.x = fmaf(g4, v4, fmaf(g3, v3, fmaf(g2, v2, fmaf(g1, v1, __fmul_rn(g0, v0)))));
            o.y = fmaf(g4, v5, fmaf(g3, v4, fmaf(g2, v3, fmaf(g1, v2, __fmul_rn(g0, v1)))));
            o.z = fmaf(g4, v6, fmaf(g3, v5, fmaf(g2, v4, fmaf(g1, v3, __fmul_rn(g0, v2)))));
            o.w = fmaf(g4, v7, fmaf(g3, v6, fmaf(g2, v5, fmaf(g1, v4, __fmul_rn(g0, v3)))));
        }
        sh4[r][cx4] = o;
    }
    __syncthreads();

    {
        int ty0 = (t >> 5) * 4;
        int tx4 = t & 31;
        float4 r0 = sh4[ty0    ][tx4];
        float4 r1 = sh4[ty0 + 1][tx4];
        float4 r2 = sh4[ty0 + 2][tx4];
        float4 r3 = sh4[ty0 + 3][tx4];
        float4 r4 = sh4[ty0 + 4][tx4];
        float4 r5 = sh4[ty0 + 5][tx4];
        float4 r6 = sh4[ty0 + 6][tx4];
        float4 r7 = sh4[ty0 + 7][tx4];
        float* base = blurred + c * HW_ + (tileY0 + ty0) * W_ + tileX0 + tx4 * 4;

#define VBLUR(d, a0, a1, a2, a3, a4)                                                               \
        {                                                                                           \
            float4 o;                                                                               \
            o.x = fmaf(g4, a4.x, fmaf(g3, a3.x, fmaf(g2, a2.x, fmaf(g1, a1.x, __fmul_rn(g0, a0.x))))); \
            o.y = fmaf(g4, a4.y, fmaf(g3, a3.y, fmaf(g2, a2.y, fmaf(g1, a1.y, __fmul_rn(g0, a0.y))))); \
            o.z = fmaf(g4, a4.z, fmaf(g3, a3.z, fmaf(g2, a2.z, fmaf(g1, a1.z, __fmul_rn(g0, a0.z))))); \
            o.w = fmaf(g4, a4.w, fmaf(g3, a3.w, fmaf(g2, a2.w, fmaf(g1, a1.w, __fmul_rn(g0, a0.w))))); \
            *(float4*)(base + (d) * W_) = o;                                                        \
        }
        VBLUR(0, r0, r1, r2, r3, r4)
        VBLUR(1, r1, r2, r3, r4, r5)
        VBLUR(2, r2, r3, r4, r5, r6)
        VBLUR(3, r3, r4, r5, r6, r7)
#undef VBLUR
    }
}

// ---------------------------------------------------------------------------
// Kernel 2: Sobel (zero pad 1) + grad_mag + orient + early_threshold.
// 4 px x 2 rows per thread: 4-row window shares the 2 interior rows between
// the two outputs (36 LDG / 8 px vs 27 / 4 px). FMA chains identical (bit-exact).
// ---------------------------------------------------------------------------
__global__ void sobel_k(const float* __restrict__ blurred,
                        const float* __restrict__ thr_p,
                        float* __restrict__ grad,
                        float* __restrict__ orient,
                        float* __restrict__ early) {
    int unit = blockIdx.x * blockDim.x + threadIdx.x;   // over (W/4) x (H/2)
    int ux = unit & (W_ / 4 - 1);       // 0..511
    int uy = unit >> (LOG2W - 2);       // 0..1023
    int x = ux * 4;
    int y = uy * 2;
    bool ym = (y > 0), yp = (y + 2 < H_);   // row y-1 valid / row y+2 valid
    bool xl = (x > 0), xr = (x + 4 < W_);

    float mag[2][4], sx[2][4], sy[2][4];
#pragma unroll
    for (int rw = 0; rw < 2; ++rw)
#pragma unroll
        for (int i = 0; i < 4; ++i) { mag[rw][i] = 0.f; sx[rw][i] = 0.f; sy[rw][i] = 0.f; }

#pragma unroll
    for (int c = 0; c < 3; ++c) {
        const float* b = blurred + c * HW_ + y * W_ + x;
        float rw0[6], rw1[6], rw2[6], rw3[6];
        // row y-1
        if (ym) {
            float4 v = __ldg((const float4*)(b - W_));
            rw0[1] = v.x; rw0[2] = v.y; rw0[3] = v.z; rw0[4] = v.w;
            rw0[0] = xl ? __ldg(b - W_ - 1) : 0.f;
            rw0[5] = xr ? __ldg(b - W_ + 4) : 0.f;
        } else {
            rw0[0] = rw0[1] = rw0[2] = rw0[3] = rw0[4] = rw0[5] = 0.f;
        }
        // row y
        {
            float4 v = __ldg((const float4*)b);
            rw1[1] = v.x; rw1[2] = v.y; rw1[3] = v.z; rw1[4] = v.w;
            rw1[0] = xl ? __ldg(b - 1) : 0.f;
            rw1[5] = xr ? __ldg(b + 4) : 0.f;
        }
        // row y+1 (always valid: y <= H-2)
        {
            float4 v = __ldg((const float4*)(b + W_));
            rw2[1] = v.x; rw2[2] = v.y; rw2[3] = v.z; rw2[4] = v.w;
            rw2[0] = xl ? __ldg(b + W_ - 1) : 0.f;
            rw2[5] = xr ? __ldg(b + W_ + 4) : 0.f;
        }
        // row y+2
        if (yp) {
            float4 v = __ldg((const float4*)(b + 2 * W_));
            rw3[1] = v.x; rw3[2] = v.y; rw3[3] = v.z; rw3[4] = v.w;
            rw3[0] = xl ? __ldg(b + 2 * W_ - 1) : 0.f;
            rw3[5] = xr ? __ldg(b + 2 * W_ + 4) : 0.f;
        } else {
            rw3[0] = rw3[1] = rw3[2] = rw3[3] = rw3[4] = rw3[5] = 0.f;
        }

#define SOBEL_ROW(rw, TP, MD, BT)                                                   \
        {                                                                            \
            _Pragma("unroll")                                                        \
            for (int i = 0; i < 4; ++i) {                                            \
                float a00 = TP[i], a01 = TP[i + 1], a02 = TP[i + 2];                 \
                float a10 = MD[i],                  a12 = MD[i + 2];                 \
                float a20 = BT[i], a21 = BT[i + 1], a22 = BT[i + 2];                 \
                float gxx = a00;                                                     \
                gxx = fmaf(-1.f, a02, gxx);                                          \
                gxx = fmaf( 2.f, a10, gxx);                                          \
                gxx = fmaf(-2.f, a12, gxx);                                          \
                gxx = fmaf( 1.f, a20, gxx);                                          \
                gxx = fmaf(-1.f, a22, gxx);                                          \
                float gyy = a00;                                                     \
                gyy = fmaf( 2.f, a01, gyy);                                          \
                gyy = fmaf( 1.f, a02, gyy);                                          \
                gyy = fmaf(-1.f, a20, gyy);                                          \
                gyy = fmaf(-2.f, a21, gyy);                                          \
                gyy = fmaf(-1.f, a22, gyy);                                          \
                mag[rw][i] = __fadd_rn(mag[rw][i], sqrtf(fmaf(gxx, gxx, __fmul_rn(gyy, gyy)))); \
                sx[rw][i]  = __fadd_rn(sx[rw][i], gxx);                              \
                sy[rw][i]  = __fadd_rn(sy[rw][i], gyy);                              \
            }                                                                        \
        }
        SOBEL_ROW(0, rw0, rw1, rw2)
        SOBEL_ROW(1, rw1, rw2, rw3)
#undef SOBEL_ROW
    }

    const float C = (float)(180.0 / 3.14159);   // NOTE: 3.14159, not pi
    float thr = __ldg(thr_p);
#pragma unroll
    for (int rw = 0; rw < 2; ++rw) {
        float4 gm4, or4, ea4;
        float* gmA = (float*)&gm4;
        float* orA = (float*)&or4;
        float* eaA = (float*)&ea4;
#pragma unroll
        for (int i = 0; i < 4; ++i) {
            float o  = atan2f(sy[rw][i], sx[rw][i]);  // libdevice __nv_atan2f
            float ov = __fmul_rn(o, C);
            float tt = __fdiv_rn(__fadd_rn(ov, 180.0f), 45.0f);
            float q  = rintf(tt);                     // half-even (jnp.round)
            gmA[i] = mag[rw][i];
            orA[i] = __fmul_rn(q, 45.0f);
            eaA[i] = (mag[rw][i] < thr) ? 0.f : mag[rw][i];
        }
        int idx = (y + rw) * W_ + x;
        *(float4*)(grad + idx)   = gm4;
        *(float4*)(orient + idx) = or4;
        *(float4*)(early + idx)  = ea4;
    }
}

// ---------------------------------------------------------------------------
// Kernel 3: NMS + threshold, 4 px/thread. Identical to R6 (bit-exact).
// Neighbors from a 3x6 register patch via nested SELs.
// dir k offsets (dy,dx): 0:(0,1) 1:(1,1) 2:(1,0) 3:(1,-1) 4:(0,-1)
//                        5:(-1,-1) 6:(-1,0) 7:(-1,1)
// ---------------------------------------------------------------------------
__global__ void nms_k(const float* __restrict__ grad,
                      const float* __restrict__ orient,
                      const float* __restrict__ thr_p,
                      float* __restrict__ thin,
                      float* __restrict__ thresh) {
    int t4 = blockIdx.x * blockDim.x + threadIdx.x;
    int idx = t4 * 4;
    int x = idx & (W_ - 1);
    int y = idx >> LOG2W;
    bool ym = (y > 0), yp = (y < H_ - 1);
    bool xl = (x > 0), xr = (x + 4 < W_);

    const unsigned DYP = 0x00012221u;   // nibble k = dy[k]+1
    const unsigned DXP = 0x21000122u;   // nibble k = dx[k]+1

    const float* b = grad + y * W_ + x;
    float tp[6], md[6], bt[6];
    if (ym) {
        float4 v = __ldg((const float4*)(b - W_));
        tp[1] = v.x; tp[2] = v.y; tp[3] = v.z; tp[4] = v.w;
        tp[0] = xl ? __ldg(b - W_ - 1) : 0.f;
        tp[5] = xr ? __ldg(b - W_ + 4) : 0.f;
    } else {
        tp[0] = tp[1] = tp[2] = tp[3] = tp[4] = tp[5] = 0.f;
    }
    {
        float4 v = __ldg((const float4*)b);
        md[1] = v.x; md[2] = v.y; md[3] = v.z; md[4] = v.w;
        md[0] = xl ? __ldg(b - 1) : 0.f;
        md[5] = xr ? __ldg(b + 4) : 0.f;
    }
    if (yp) {
        float4 v = __ldg((const float4*)(b + W_));
        bt[1] = v.x; bt[2] = v.y; bt[3] = v.z; bt[4] = v.w;
        bt[0] = xl ? __ldg(b + W_ - 1) : 0.f;
        bt[5] = xr ? __ldg(b + W_ + 4) : 0.f;
    } else {
        bt[0] = bt[1] = bt[2] = bt[3] = bt[4] = bt[5] = 0.f;
    }

    float4 or4 = __ldg((const float4*)(orient + idx));
    float thr = __ldg(thr_p);
    const float* orA = (const float*)&or4;

    float4 th4, ts4;
    float* thA = (float*)&th4;
    float* tsA = (float*)&ts4;
#pragma unroll
    for (int i = 0; i < 4; ++i) {
        float gm = md[i + 1];
        int q  = (int)(orA[i] * (1.0f / 45.0f));   // orient = 45*q exactly
        int kp = q & 7;
        int kn = (q + 4) & 7;

        int dyp = (int)((DYP >> (kp * 4)) & 3u) - 1;
        int dxp = (int)((DXP >> (kp * 4)) & 3u) - 1;
        int dyn = (int)((DYP >> (kn * 4)) & 3u) - 1;
        int dxn = (int)((DXP >> (kn * 4)) & 3u) - 1;

        float tT = (dxp < 0) ? tp[i] : ((dxp > 0) ? tp[i + 2] : tp[i + 1]);
        float tM = (dxp < 0) ? md[i] : ((dxp > 0) ? md[i + 2] : md[i + 1]);
        float tB = (dxp < 0) ? bt[i] : ((dxp > 0) ? bt[i + 2] : bt[i + 1]);
        float np = (dyp < 0) ? tT : ((dyp > 0) ? tB : tM);

        float uT = (dxn < 0) ? tp[i] : ((dxn > 0) ? tp[i + 2] : tp[i + 1]);
        float uM = (dxn < 0) ? md[i] : ((dxn > 0) ? md[i + 2] : md[i + 1]);
        float uB = (dxn < 0) ? bt[i] : ((dxn > 0) ? bt[i + 2] : bt[i + 1]);
        float nn = (dyn < 0) ? uT : ((dyn > 0) ? uB : uM);

        float pos = __fadd_rn(gm, -np);
        float neg = __fadd_rn(gm, -nn);
        float tv = (fminf(pos, neg) > 0.f) ? gm : 0.f;
        thA[i] = tv;
        tsA[i] = (tv < thr) ? 0.f : tv;
    }
    *(float4*)(thin + idx)   = th4;
    *(float4*)(thresh + idx) = ts4;
}

// ---------------------------------------------------------------------------
// Launch
// Inputs: img[3HW], threshold[1], gauss_h[5], gauss_v[5], sobel_h[9],
//         sobel_v[9], dir_w[72]
// Output: [0,3HW) blurred | [3HW,4HW) grad | [4HW,5HW) orient |
//         [5HW,6HW) thin | [6HW,7HW) thresholded | [7HW,8HW) early
// ---------------------------------------------------------------------------
extern "C" void kernel_launch(void* const* d_in, const int* in_sizes, int n_in,
                              void* d_out, int out_size) {
    const float* img   = (const float*)d_in[0];
    const float* thr   = (const float*)d_in[1];
    const float* gauss = (const float*)d_in[2];

    float* out      = (float*)d_out;
    float* blurred  = out;
    float* grad     = out + 3 * HW_;
    float* orient   = out + 4 * HW_;
    float* thin     = out + 5 * HW_;
    float* thresh   = out + 6 * HW_;
    float* early    = out + 7 * HW_;

    dim3 bgrid(W_ / TILE_X, H_ / TILE_Y, 3);   // 16 x 64 x 3
    blur_f_k<<<bgrid, 256>>>(img, gauss, blurred);

    int sunits = (W_ / 4) * (H_ / 2);           // 524288
    sobel_k<<<sunits / 256, 256>>>(blurred, thr, grad, orient, early);

    int blocks1 = (HW_ / 4 + 255) / 256;        // 4096
    nms_k<<<blocks1, 256>>>(grad, orient, thr, thin, thresh);
}

// round 9
// speedup vs baseline: 1.2646x; 1.0326x over previous
#include <cuda_runtime.h>
#include <math.h>

// Problem constants (fixed by reference: H = W = 2048)
#define H_ 2048
#define W_ 2048
#define HW_ (H_ * W_)
#define LOG2W 11

// Packed 3-bit direction indices (one byte per pixel), written by sobel,
// consumed by nms. 4 MB static scratch (allowed).
__device__ unsigned char g_q[HW_];

// ---------------------------------------------------------------------------
// Kernel 1: fused separable gaussian (1x5 then 5x1, zero pad 2).
// Tile 128x32 per block/channel. Identical to R6 (bit-exact).
// ---------------------------------------------------------------------------
#define TILE_X 128
#define TILE_Y 32
#define SROWS (TILE_Y + 4)
#define TX4 (TILE_X / 4)

__global__ void blur_f_k(const float* __restrict__ img, const float* __restrict__ g,
                         float* __restrict__ blurred) {
    __shared__ float4 sh4[SROWS][TX4];
    const int c = blockIdx.z;
    const int tileX0 = blockIdx.x * TILE_X;
    const int tileY0 = blockIdx.y * TILE_Y;
    const int t = threadIdx.x;          // 0..255
    const float* im = img + c * HW_;
    const float g0 = g[0], g1 = g[1], g2 = g[2], g3 = g[3], g4 = g[4];
    const float4 z4 = make_float4(0.f, 0.f, 0.f, 0.f);

    for (int u = t; u < SROWS * TX4; u += 256) {
        int r   = u >> 5;
        int cx4 = u & 31;
        int gy  = tileY0 - 2 + r;
        float4 o = z4;
        if (gy >= 0 && gy < H_) {
            const float4* row4 = (const float4*)(im + gy * W_);
            int gx = tileX0 + cx4 * 4;
            float4 L = (gx >= 4)     ? __ldg(row4 + (gx >> 2) - 1) : z4;
            float4 M =                 __ldg(row4 + (gx >> 2));
            float4 R = (gx + 4 < W_) ? __ldg(row4 + (gx >> 2) + 1) : z4;
            float v0 = L.z, v1 = L.w;
            float v2 = M.x, v3 = M.y, v4 = M.z, v5 = M.w;
            float v6 = R.x, v7 = R.y;
            o.x = fmaf(g4, v4, fmaf(g3, v3, fmaf(g2, v2, fmaf(g1, v1, __fmul_rn(g0, v0)))));
            o.y = fmaf(g4, v5, fmaf(g3, v4, fmaf(g2, v3, fmaf(g1, v2, __fmul_rn(g0, v1)))));
            o.z = fmaf(g4, v6, fmaf(g3, v5, fmaf(g2, v4, fmaf(g1, v3, __fmul_rn(g0, v2)))));
            o.w = fmaf(g4, v7, fmaf(g3, v6, fmaf(g2, v5, fmaf(g1, v4, __fmul_rn(g0, v3)))));
        }
        sh4[r][cx4] = o;
    }
    __syncthreads();

    {
        int ty0 = (t >> 5) * 4;
        int tx4 = t & 31;
        float4 r0 = sh4[ty0    ][tx4];
        float4 r1 = sh4[ty0 + 1][tx4];
        float4 r2 = sh4[ty0 + 2][tx4];
        float4 r3 = sh4[ty0 + 3][tx4];
        float4 r4 = sh4[ty0 + 4][tx4];
        float4 r5 = sh4[ty0 + 5][tx4];
        float4 r6 = sh4[ty0 + 6][tx4];
        float4 r7 = sh4[ty0 + 7][tx4];
        float* base = blurred + c * HW_ + (tileY0 + ty0) * W_ + tileX0 + tx4 * 4;

#define VBLUR(d, a0, a1, a2, a3, a4)                                                               \
        {                                                                                           \
            float4 o;                                                                               \
            o.x = fmaf(g4, a4.x, fmaf(g3, a3.x, fmaf(g2, a2.x, fmaf(g1, a1.x, __fmul_rn(g0, a0.x))))); \
            o.y = fmaf(g4, a4.y, fmaf(g3, a3.y, fmaf(g2, a2.y, fmaf(g1, a1.y, __fmul_rn(g0, a0.y))))); \
            o.z = fmaf(g4, a4.z, fmaf(g3, a3.z, fmaf(g2, a2.z, fmaf(g1, a1.z, __fmul_rn(g0, a0.z))))); \
            o.w = fmaf(g4, a4.w, fmaf(g3, a3.w, fmaf(g2, a2.w, fmaf(g1, a1.w, __fmul_rn(g0, a0.w))))); \
            *(float4*)(base + (d) * W_) = o;                                                        \
        }
        VBLUR(0, r0, r1, r2, r3, r4)
        VBLUR(1, r1, r2, r3, r4, r5)
        VBLUR(2, r2, r3, r4, r5, r6)
        VBLUR(3, r3, r4, r5, r6, r7)
#undef VBLUR
    }
}

// ---------------------------------------------------------------------------
// Kernel 2: Sobel (zero pad 1) + grad_mag + orient + early_threshold.
// 4 px/thread (R6 form), plus a packed q-byte store for nms.
// FMA chains identical (bit-exact).
// ---------------------------------------------------------------------------
__global__ void sobel_k(const float* __restrict__ blurred,
                        const float* __restrict__ thr_p,
                        float* __restrict__ grad,
                        float* __restrict__ orient,
                        float* __restrict__ early) {
    int t4 = blockIdx.x * blockDim.x + threadIdx.x;   // float4 index
    int idx = t4 * 4;
    int x = idx & (W_ - 1);
    int y = idx >> LOG2W;
    bool ym = (y > 0), yp = (y < H_ - 1);
    bool xl = (x > 0), xr = (x + 4 < W_);

    float mag[4] = {0.f, 0.f, 0.f, 0.f};
    float sx[4]  = {0.f, 0.f, 0.f, 0.f};
    float sy[4]  = {0.f, 0.f, 0.f, 0.f};

#pragma unroll
    for (int c = 0; c < 3; ++c) {
        const float* b = blurred + c * HW_ + y * W_ + x;
        float tp[6], md[6], bt[6];
        if (ym) {
            float4 v = __ldg((const float4*)(b - W_));
            tp[1] = v.x; tp[2] = v.y; tp[3] = v.z; tp[4] = v.w;
            tp[0] = xl ? __ldg(b - W_ - 1) : 0.f;
            tp[5] = xr ? __ldg(b - W_ + 4) : 0.f;
        } else {
            tp[0] = tp[1] = tp[2] = tp[3] = tp[4] = tp[5] = 0.f;
        }
        {
            float4 v = __ldg((const float4*)b);
            md[1] = v.x; md[2] = v.y; md[3] = v.z; md[4] = v.w;
            md[0] = xl ? __ldg(b - 1) : 0.f;
            md[5] = xr ? __ldg(b + 4) : 0.f;
        }
        if (yp) {
            float4 v = __ldg((const float4*)(b + W_));
            bt[1] = v.x; bt[2] = v.y; bt[3] = v.z; bt[4] = v.w;
            bt[0] = xl ? __ldg(b + W_ - 1) : 0.f;
            bt[5] = xr ? __ldg(b + W_ + 4) : 0.f;
        } else {
            bt[0] = bt[1] = bt[2] = bt[3] = bt[4] = bt[5] = 0.f;
        }
#pragma unroll
        for (int i = 0; i < 4; ++i) {
            float a00 = tp[i], a01 = tp[i + 1], a02 = tp[i + 2];
            float a10 = md[i],                  a12 = md[i + 2];
            float a20 = bt[i], a21 = bt[i + 1], a22 = bt[i + 2];
            float gx = a00;
            gx = fmaf(-1.f, a02, gx);
            gx = fmaf( 2.f, a10, gx);
            gx = fmaf(-2.f, a12, gx);
            gx = fmaf( 1.f, a20, gx);
            gx = fmaf(-1.f, a22, gx);
            float gy = a00;
            gy = fmaf( 2.f, a01, gy);
            gy = fmaf( 1.f, a02, gy);
            gy = fmaf(-1.f, a20, gy);
            gy = fmaf(-2.f, a21, gy);
            gy = fmaf(-1.f, a22, gy);

            mag[i] = __fadd_rn(mag[i], sqrtf(fmaf(gx, gx, __fmul_rn(gy, gy))));
            sx[i]  = __fadd_rn(sx[i], gx);
            sy[i]  = __fadd_rn(sy[i], gy);
        }
    }

    const float C = (float)(180.0 / 3.14159);   // NOTE: 3.14159, not pi
    float thr = __ldg(thr_p);
    float4 gm4, or4, ea4;
    float* gmA = (float*)&gm4;
    float* orA = (float*)&or4;
    float* eaA = (float*)&ea4;
    unsigned qpack = 0;
#pragma unroll
    for (int i = 0; i < 4; ++i) {
        float o  = atan2f(sy[i], sx[i]);         // libdevice __nv_atan2f (same as XLA)
        float ov = __fmul_rn(o, C);
        float tt = __fdiv_rn(__fadd_rn(ov, 180.0f), 45.0f);
        float q  = rintf(tt);                    // half-even (jnp.round)
        gmA[i] = mag[i];
        orA[i] = __fmul_rn(q, 45.0f);
        eaA[i] = (mag[i] < thr) ? 0.f : mag[i];
        qpack |= ((unsigned)(int)q) << (i * 8);  // q in [0,8]
    }
    *(float4*)(grad + idx)   = gm4;
    *(float4*)(orient + idx) = or4;
    *(float4*)(early + idx)  = ea4;
    *(unsigned*)(g_q + idx)  = qpack;
}

// ---------------------------------------------------------------------------
// Kernel 3: NMS + threshold, 4 px/thread. Neighbors from a 3x6 register
// patch via nested SELs; q indices from the packed byte map (no orient load).
// dir k offsets (dy,dx): 0:(0,1) 1:(1,1) 2:(1,0) 3:(1,-1) 4:(0,-1)
//                        5:(-1,-1) 6:(-1,0) 7:(-1,1)
// ---------------------------------------------------------------------------
__global__ void nms_k(const float* __restrict__ grad,
                      const float* __restrict__ thr_p,
                      float* __restrict__ thin,
                      float* __restrict__ thresh) {
    int t4 = blockIdx.x * blockDim.x + threadIdx.x;
    int idx = t4 * 4;
    int x = idx & (W_ - 1);
    int y = idx >> LOG2W;
    bool ym = (y > 0), yp = (y < H_ - 1);
    bool xl = (x > 0), xr = (x + 4 < W_);

    const unsigned DYP = 0x00012221u;   // nibble k = dy[k]+1
    const unsigned DXP = 0x21000122u;   // nibble k = dx[k]+1

    const float* b = grad + y * W_ + x;
    float tp[6], md[6], bt[6];
    if (ym) {
        float4 v = __ldg((const float4*)(b - W_));
        tp[1] = v.x; tp[2] = v.y; tp[3] = v.z; tp[4] = v.w;
        tp[0] = xl ? __ldg(b - W_ - 1) : 0.f;
        tp[5] = xr ? __ldg(b - W_ + 4) : 0.f;
    } else {
        tp[0] = tp[1] = tp[2] = tp[3] = tp[4] = tp[5] = 0.f;
    }
    {
        float4 v = __ldg((const float4*)b);
        md[1] = v.x; md[2] = v.y; md[3] = v.z; md[4] = v.w;
        md[0] = xl ? __ldg(b - 1) : 0.f;
        md[5] = xr ? __ldg(b + 4) : 0.f;
    }
    if (yp) {
        float4 v = __ldg((const float4*)(b + W_));
        bt[1] = v.x; bt[2] = v.y; bt[3] = v.z; bt[4] = v.w;
        bt[0] = xl ? __ldg(b + W_ - 1) : 0.f;
        bt[5] = xr ? __ldg(b + W_ + 4) : 0.f;
    } else {
        bt[0] = bt[1] = bt[2] = bt[3] = bt[4] = bt[5] = 0.f;
    }

    unsigned qpack = *(const unsigned*)(g_q + idx);
    float thr = __ldg(thr_p);

    float4 th4, ts4;
    float* thA = (float*)&th4;
    float* tsA = (float*)&ts4;
#pragma unroll
    for (int i = 0; i < 4; ++i) {
        float gm = md[i + 1];
        int q  = (int)((qpack >> (i * 8)) & 0xFFu);
        int kp = q & 7;
        int kn = (q + 4) & 7;

        int dyp = (int)((DYP >> (kp * 4)) & 3u) - 1;
        int dxp = (int)((DXP >> (kp * 4)) & 3u) - 1;
        int dyn = (int)((DYP >> (kn * 4)) & 3u) - 1;
        int dxn = (int)((DXP >> (kn * 4)) & 3u) - 1;

        float tT = (dxp < 0) ? tp[i] : ((dxp > 0) ? tp[i + 2] : tp[i + 1]);
        float tM = (dxp < 0) ? md[i] : ((dxp > 0) ? md[i + 2] : md[i + 1]);
        float tB = (dxp < 0) ? bt[i] : ((dxp > 0) ? bt[i + 2] : bt[i + 1]);
        float np = (dyp < 0) ? tT : ((dyp > 0) ? tB : tM);

        float uT = (dxn < 0) ? tp[i] : ((dxn > 0) ? tp[i + 2] : tp[i + 1]);
        float uM = (dxn < 0) ? md[i] : ((dxn > 0) ? md[i + 2] : md[i + 1]);
        float uB = (dxn < 0) ? bt[i] : ((dxn > 0) ? bt[i + 2] : bt[i + 1]);
        float nn = (dyn < 0) ? uT : ((dyn > 0) ? uB : uM);

        float pos = __fadd_rn(gm, -np);
        float neg = __fadd_rn(gm, -nn);
        float tv = (fminf(pos, neg) > 0.f) ? gm : 0.f;
        thA[i] = tv;
        tsA[i] = (tv < thr) ? 0.f : tv;
    }
    *(float4*)(thin + idx)   = th4;
    *(float4*)(thresh + idx) = ts4;
}

// ---------------------------------------------------------------------------
// Launch
// Inputs: img[3HW], threshold[1], gauss_h[5], gauss_v[5], sobel_h[9],
//         sobel_v[9], dir_w[72]
// Output: [0,3HW) blurred | [3HW,4HW) grad | [4HW,5HW) orient |
//         [5HW,6HW) thin | [6HW,7HW) thresholded | [7HW,8HW) early
// ---------------------------------------------------------------------------
extern "C" void kernel_launch(void* const* d_in, const int* in_sizes, int n_in,
                              void* d_out, int out_size) {
    const float* img   = (const float*)d_in[0];
    const float* thr   = (const float*)d_in[1];
    const float* gauss = (const float*)d_in[2];

    float* out      = (float*)d_out;
    float* blurred  = out;
    float* grad     = out + 3 * HW_;
    float* orient   = out + 4 * HW_;
    float* thin     = out + 5 * HW_;
    float* thresh   = out + 6 * HW_;
    float* early    = out + 7 * HW_;

    dim3 bgrid(W_ / TILE_X, H_ / TILE_Y, 3);   // 16 x 64 x 3
    blur_f_k<<<bgrid, 256>>>(img, gauss, blurred);

    int blocks1 = (HW_ / 4 + 255) / 256;        // 4096
    sobel_k<<<blocks1, 256>>>(blurred, thr, grad, orient, early);
    nms_k<<<blocks1, 256>>>(grad, thr, thin, thresh);
}